// round 1
// baseline (speedup 1.0000x reference)
#include <cuda_runtime.h>
#include <cstdint>

// out[b] = a[b] @ x[b] :  a [8,4096,4096] f32, x [8,4096,32] f32, out [8,4096,32] f32
// tf32 mma.sync with A hi/lo split (error ~1e-4), cp.async double-buffered pipeline.

#define DEV __device__ __forceinline__

constexpr int Bsz = 8;
constexpr int Nn  = 4096;
constexpr int Dd  = 32;
constexpr int Kk  = 4096;

constexpr int BM  = 64;      // n-rows per block
constexpr int BK  = 32;      // k per pipeline stage
constexpr int NIT = Kk / BK; // 128
constexpr int THREADS = 128; // 4 warps, each owns 16 rows (one m16 tile)
constexpr int XS_STRIDE = 40; // padded row stride (floats) for conflict-free B reads

DEV uint32_t cvta_s(const void* p) { return (uint32_t)__cvta_generic_to_shared(p); }

DEV void cp16(uint32_t dst, const void* src) {
    asm volatile("cp.async.cg.shared.global [%0], [%1], 16;\n" :: "r"(dst), "l"(src));
}
DEV void cp_commit() { asm volatile("cp.async.commit_group;\n" ::: "memory"); }
DEV void cp_wait0()  { asm volatile("cp.async.wait_group 0;\n" ::: "memory"); }

#define MMA_TF32(C, A0, A1, A2, A3, B0, B1)                                    \
    asm volatile(                                                              \
        "mma.sync.aligned.m16n8k8.row.col.f32.tf32.tf32.f32 "                  \
        "{%0,%1,%2,%3}, {%4,%5,%6,%7}, {%8,%9}, {%0,%1,%2,%3};\n"              \
        : "+f"(C[0]), "+f"(C[1]), "+f"(C[2]), "+f"(C[3])                       \
        : "r"(A0), "r"(A1), "r"(A2), "r"(A3), "r"(B0), "r"(B1))

__global__ __launch_bounds__(THREADS)
void gsum_tf32_kernel(const float* __restrict__ x,
                      const float* __restrict__ a,
                      float* __restrict__ out)
{
    // A tile: [BM][BK] floats, xor-swizzled on float4 index (row stride 32 floats = 128B)
    __shared__ float As[2][BM * BK];
    // X tile: [BK][XS_STRIDE] floats (natural [k][d] layout, padded)
    __shared__ float Xs[2][BK * XS_STRIDE];

    const int tid  = threadIdx.x;
    const int warp = tid >> 5;
    const int lane = tid & 31;

    const int b  = blockIdx.y;
    const int n0 = blockIdx.x * BM;

    const float* Ab = a + ((size_t)b * Nn + n0) * (size_t)Kk;
    const float* Xb = x + (size_t)b * Kk * Dd;

    float acc[4][4];
#pragma unroll
    for (int i = 0; i < 4; i++)
#pragma unroll
        for (int j = 0; j < 4; j++) acc[i][j] = 0.f;

    // ldmatrix.x4 lane -> (row within m16 tile, k-subgroup) mapping:
    // lanes 0-7: rows 0-7 g+0 | 8-15: rows 8-15 g+0 | 16-23: rows 0-7 g+1 | 24-31: rows 8-15 g+1
    const int lm_row = (lane & 7) + (((lane >> 3) & 1) << 3);
    const int lm_g   = lane >> 4;               // 0 or 1
    const int a_row  = warp * 16 + lm_row;      // row within As tile

    const int tig = lane & 3;   // thread-in-group (k index within k4)
    const int gid = lane >> 2;  // group id (n index within n8)

#define ISSUE_LOADS(it_, buf_)                                                   \
    do {                                                                         \
        const int k0_ = (it_) * BK;                                              \
        _Pragma("unroll")                                                        \
        for (int i_ = 0; i_ < 4; i_++) { /* A: 64x32 = 512 chunks of 16B */      \
            int idx_ = i_ * THREADS + tid;                                       \
            int row_ = idx_ >> 3, c4_ = idx_ & 7;                                \
            const float* src_ = Ab + (size_t)row_ * Kk + k0_ + c4_ * 4;          \
            uint32_t dst_ = cvta_s(&As[buf_][row_ * BK + ((c4_ ^ (row_ & 7)) << 2)]); \
            cp16(dst_, src_);                                                    \
        }                                                                        \
        _Pragma("unroll")                                                        \
        for (int i_ = 0; i_ < 2; i_++) { /* X: 32x32 = 256 chunks of 16B */      \
            int idx_ = i_ * THREADS + tid;                                       \
            int kr_ = idx_ >> 3, c4_ = idx_ & 7;                                 \
            const float* src_ = Xb + (size_t)(k0_ + kr_) * Dd + c4_ * 4;         \
            uint32_t dst_ = cvta_s(&Xs[buf_][kr_ * XS_STRIDE + c4_ * 4]);        \
            cp16(dst_, src_);                                                    \
        }                                                                        \
        cp_commit();                                                             \
    } while (0)

    ISSUE_LOADS(0, 0);
    cp_wait0();
    __syncthreads();

#pragma unroll 1
    for (int it = 0; it < NIT; ++it) {
        const int cur = it & 1;
        if (it + 1 < NIT) ISSUE_LOADS(it + 1, cur ^ 1);

#pragma unroll
        for (int ks = 0; ks < 4; ++ks) {
            // --- A fragment via ldmatrix.x4 (tf32 as pairs of b16) ---
            uint32_t ar[4];
            {
                int g = ks * 2 + lm_g;  // float4-group within the 32-float row
                uint32_t addr = cvta_s(&As[cur][a_row * BK + ((g ^ (a_row & 7)) << 2)]);
                asm volatile(
                    "ldmatrix.sync.aligned.m8n8.x4.shared.b16 {%0,%1,%2,%3}, [%4];\n"
                    : "=r"(ar[0]), "=r"(ar[1]), "=r"(ar[2]), "=r"(ar[3])
                    : "r"(addr));
            }
            // exact hi/lo split: hi = top tf32 bits, lo = a - hi (exact in fp32)
            uint32_t ah[4], al[4];
#pragma unroll
            for (int j = 0; j < 4; j++) {
                ah[j] = ar[j] & 0xffffe000u;
                al[j] = __float_as_uint(__uint_as_float(ar[j]) - __uint_as_float(ah[j]));
            }

            // --- B fragments: Xs[k][d], k = ks*8 + tig (+4), d = gid + ni*8 ---
            const float* xrow = &Xs[cur][(ks * 8 + tig) * XS_STRIDE + gid];
#pragma unroll
            for (int ni = 0; ni < 4; ++ni) {
                float b0f = xrow[ni * 8];
                float b1f = xrow[4 * XS_STRIDE + ni * 8];
                uint32_t b0, b1;
                asm("cvt.rna.tf32.f32 %0, %1;" : "=r"(b0) : "f"(b0f));
                asm("cvt.rna.tf32.f32 %0, %1;" : "=r"(b1) : "f"(b1f));
                MMA_TF32(acc[ni], ah[0], ah[1], ah[2], ah[3], b0, b1);
                MMA_TF32(acc[ni], al[0], al[1], al[2], al[3], b0, b1);
            }
        }

        cp_wait0();
        __syncthreads();
    }

    // --- epilogue: C fragment (m16n8): c0/c1 at (row, 2*tig(+1)), c2/c3 at row+8 ---
    const int orow = n0 + warp * 16 + gid;
    float* ob = out + (size_t)b * Nn * Dd;
#pragma unroll
    for (int ni = 0; ni < 4; ++ni) {
        int col = ni * 8 + tig * 2;
        *reinterpret_cast<float2*>(&ob[(size_t)orow * Dd + col]) =
            make_float2(acc[ni][0], acc[ni][1]);
        *reinterpret_cast<float2*>(&ob[(size_t)(orow + 8) * Dd + col]) =
            make_float2(acc[ni][2], acc[ni][3]);
    }
}

extern "C" void kernel_launch(void* const* d_in, const int* in_sizes, int n_in,
                              void* d_out, int out_size)
{
    // x has 1,048,576 elems; a has 134,217,728 — select by size for robustness.
    const float* x;
    const float* a;
    if (in_sizes[0] < in_sizes[1]) {
        x = (const float*)d_in[0];
        a = (const float*)d_in[1];
    } else {
        x = (const float*)d_in[1];
        a = (const float*)d_in[0];
    }
    dim3 grid(Nn / BM, Bsz);
    gsum_tf32_kernel<<<grid, THREADS>>>(x, a, (float*)d_out);
}

// round 2
// speedup vs baseline: 1.3650x; 1.3650x over previous
#include <cuda_runtime.h>
#include <cstdint>

// out[b] = a[b] @ x[b] :  a [8,4096,4096] f32, x [8,4096,32] f32, out [8,4096,32] f32
// tf32 mma.sync (rna-rounded both operands), 4-stage cp.async pipeline.

#define DEV __device__ __forceinline__

constexpr int Bsz = 8;
constexpr int Nn  = 4096;
constexpr int Dd  = 32;
constexpr int Kk  = 4096;

constexpr int BM  = 64;      // n-rows per block
constexpr int BK  = 32;      // k per pipeline stage
constexpr int NIT = Kk / BK; // 128
constexpr int THREADS = 128; // 4 warps, each owns one m16 tile
constexpr int STAGES = 4;
constexpr int XS_STRIDE = 40;           // padded X row stride (floats)

constexpr int A_STAGE  = BM * BK;        // floats per A stage (2048)
constexpr int X_STAGE  = BK * XS_STRIDE; // floats per X stage (1280)
constexpr int A_STAGE_B = A_STAGE * 4;   // 8192 B
constexpr int X_STAGE_B = X_STAGE * 4;   // 5120 B
constexpr int SMEM_BYTES = STAGES * (A_STAGE_B + X_STAGE_B); // 53248 B

DEV uint32_t cvta_s(const void* p) { return (uint32_t)__cvta_generic_to_shared(p); }

DEV void cp16(uint32_t dst, const void* src) {
    asm volatile("cp.async.cg.shared.global [%0], [%1], 16;\n" :: "r"(dst), "l"(src));
}
DEV void cp_commit() { asm volatile("cp.async.commit_group;\n" ::: "memory"); }

#define MMA_TF32(C, A0, A1, A2, A3, B0, B1)                                    \
    asm volatile(                                                              \
        "mma.sync.aligned.m16n8k8.row.col.f32.tf32.tf32.f32 "                  \
        "{%0,%1,%2,%3}, {%4,%5,%6,%7}, {%8,%9}, {%0,%1,%2,%3};\n"              \
        : "+f"(C[0]), "+f"(C[1]), "+f"(C[2]), "+f"(C[3])                       \
        : "r"(A0), "r"(A1), "r"(A2), "r"(A3), "r"(B0), "r"(B1))

__global__ __launch_bounds__(THREADS)
void gsum_tf32_kernel(const float* __restrict__ x,
                      const float* __restrict__ a,
                      float* __restrict__ out)
{
    extern __shared__ float smem[];
    float* As = smem;                         // [STAGES][A_STAGE], xor-swizzled rows
    float* Xs = smem + STAGES * A_STAGE;      // [STAGES][BK][XS_STRIDE]
    const uint32_t As_base = cvta_s(As);
    const uint32_t Xs_base = cvta_s(Xs);

    const int tid  = threadIdx.x;
    const int warp = tid >> 5;
    const int lane = tid & 31;

    const int b  = blockIdx.y;
    const int n0 = blockIdx.x * BM;

    const float* Ab = a + ((size_t)b * Nn + n0) * (size_t)Kk;
    const float* Xb = x + (size_t)b * Kk * Dd;

    // ---- precompute per-thread cp.async (src, dst-offset) pairs ----
    const float* a_src[4]; uint32_t a_off[4];
#pragma unroll
    for (int i = 0; i < 4; i++) {            // A: 64x32 = 512 chunks of 16B
        int idx = i * THREADS + tid;
        int row = idx >> 3, c4 = idx & 7;
        a_src[i] = Ab + (size_t)row * Kk + c4 * 4;
        a_off[i] = (uint32_t)((row * BK + ((c4 ^ (row & 7)) << 2)) * 4);
    }
    const float* x_src[2]; uint32_t x_off[2];
#pragma unroll
    for (int i = 0; i < 2; i++) {            // X: 32x32 = 256 chunks of 16B
        int idx = i * THREADS + tid;
        int kr = idx >> 3, c4 = idx & 7;
        x_src[i] = Xb + (size_t)kr * Dd + c4 * 4;
        x_off[i] = (uint32_t)((kr * XS_STRIDE + c4 * 4) * 4);
    }

    float acc[4][4];
#pragma unroll
    for (int i = 0; i < 4; i++)
#pragma unroll
        for (int j = 0; j < 4; j++) acc[i][j] = 0.f;

    // ldmatrix.x4 lane mapping
    const int lm_row = (lane & 7) + (((lane >> 3) & 1) << 3);
    const int lm_g   = lane >> 4;
    const int a_row  = warp * 16 + lm_row;
    const uint32_t a_row_off = (uint32_t)(a_row * BK * 4);
    const int a_sw  = a_row & 7;

    const int tig = lane & 3;   // k within k4
    const int gid = lane >> 2;  // n within n8

#define ISSUE_LOADS(it_, buf_)                                                 \
    do {                                                                       \
        uint32_t abase_ = As_base + (buf_) * A_STAGE_B;                        \
        uint32_t xbase_ = Xs_base + (buf_) * X_STAGE_B;                        \
        _Pragma("unroll")                                                      \
        for (int i_ = 0; i_ < 4; i_++)                                         \
            cp16(abase_ + a_off[i_], a_src[i_] + (it_) * BK);                  \
        _Pragma("unroll")                                                      \
        for (int i_ = 0; i_ < 2; i_++)                                         \
            cp16(xbase_ + x_off[i_], x_src[i_] + (it_) * (BK * Dd));           \
        cp_commit();                                                           \
    } while (0)

    // prologue: fill STAGES-1 stages
#pragma unroll
    for (int s = 0; s < STAGES - 1; ++s) ISSUE_LOADS(s, s);

#pragma unroll 1
    for (int it = 0; it < NIT; ++it) {
        asm volatile("cp.async.wait_group %0;\n" :: "n"(STAGES - 2) : "memory");
        __syncthreads();

        const int nxt = it + STAGES - 1;
        if (nxt < NIT) ISSUE_LOADS(nxt, nxt & (STAGES - 1));
        else cp_commit();   // keep group arithmetic consistent at tail

        const int cur = it & (STAGES - 1);
        const uint32_t a_cur = As_base + cur * A_STAGE_B + a_row_off;
        const float* x_cur = Xs + cur * X_STAGE + gid;

#pragma unroll
        for (int ks = 0; ks < 4; ++ks) {
            uint32_t ar[4];
            {
                int col4 = (ks * 2 + lm_g) ^ a_sw;
                asm volatile(
                    "ldmatrix.sync.aligned.m8n8.x4.shared.b16 {%0,%1,%2,%3}, [%4];\n"
                    : "=r"(ar[0]), "=r"(ar[1]), "=r"(ar[2]), "=r"(ar[3])
                    : "r"(a_cur + col4 * 16));
            }
            uint32_t at[4];
#pragma unroll
            for (int j = 0; j < 4; j++)
                asm("cvt.rna.tf32.f32 %0, %1;" : "=r"(at[j]) : "f"(__uint_as_float(ar[j])));

            const float* xrow = x_cur + (ks * 8 + tig) * XS_STRIDE;
#pragma unroll
            for (int ni = 0; ni < 4; ++ni) {
                float b0f = xrow[ni * 8];
                float b1f = xrow[4 * XS_STRIDE + ni * 8];
                uint32_t b0, b1;
                asm("cvt.rna.tf32.f32 %0, %1;" : "=r"(b0) : "f"(b0f));
                asm("cvt.rna.tf32.f32 %0, %1;" : "=r"(b1) : "f"(b1f));
                MMA_TF32(acc[ni], at[0], at[1], at[2], at[3], b0, b1);
            }
        }
    }

    // ---- epilogue ----
    const int orow = n0 + warp * 16 + gid;
    float* ob = out + (size_t)b * Nn * Dd;
#pragma unroll
    for (int ni = 0; ni < 4; ++ni) {
        int col = ni * 8 + tig * 2;
        *reinterpret_cast<float2*>(&ob[(size_t)orow * Dd + col]) =
            make_float2(acc[ni][0], acc[ni][1]);
        *reinterpret_cast<float2*>(&ob[(size_t)(orow + 8) * Dd + col]) =
            make_float2(acc[ni][2], acc[ni][3]);
    }
}

extern "C" void kernel_launch(void* const* d_in, const int* in_sizes, int n_in,
                              void* d_out, int out_size)
{
    const float* x;
    const float* a;
    if (in_sizes[0] < in_sizes[1]) {
        x = (const float*)d_in[0];
        a = (const float*)d_in[1];
    } else {
        x = (const float*)d_in[1];
        a = (const float*)d_in[0];
    }
    cudaFuncSetAttribute(gsum_tf32_kernel,
                         cudaFuncAttributeMaxDynamicSharedMemorySize, SMEM_BYTES);
    dim3 grid(Nn / BM, Bsz);
    gsum_tf32_kernel<<<grid, THREADS, SMEM_BYTES>>>(x, a, (float*)d_out);
}